// round 15
// baseline (speedup 1.0000x reference)
#include <cuda_runtime.h>

// 2-layer LSTM (B=2048, T=1024, I=6, H=38) + projection (C=8), fp32.
// grid=128 persistent blocks, 16 batches/block, 320 threads, ONE barrier/step.
//   group A (0..159):   layer 0 @ step t
//   group B (160..319): layer 1 @ step t-1
// x/h0/h1 double-buffered by parity; reads p, writes nb.
// NEW: state stored DUPLICATED in smem ({v,v} pairs, 32-float rows) so the
// h operand loads ready-packed for fma.rn.f32x2 -> NO register splats.
// Thread = (px 0..3, q 0..39), owns 4 batches. Per k:
//   2x LDS.128 h dup ({h0,h0,h1,h1},{h2,h2,h3,h3}) + 1x LDS.128 W
//   + 8x fma.rn.f32x2  =  11 instructions / 16 MACs  (was 14).

namespace {
constexpr int Bsz = 2048, Tt = 1024, NI = 6, H = 38, HP = 40, Cc = 8;
constexpr int BT = 16;             // batches per block
constexpr int RW = 2 * BT;         // duplicated row width = 32 floats (128 B)
constexpr int GRP = 160;           // threads per group
constexpr int NTHR = 2 * GRP;      // 320
constexpr int WAN = (NI + HP) * HP * 4;   // 7360 floats
constexpr int WBN = (HP + HP) * HP * 4;   // 12800 floats
// s0 rows (RW floats each): x dbl-buf [0..2*NI), h0 dbl-buf [2*NI..2*NI+2*HP)
// s1 rows: h1 dbl-buf [0..2*HP)
constexpr int S0ROWS = 2 * NI + 2 * HP;   // 92
constexpr int S1ROWS = 2 * HP;            // 80
constexpr int S0N = S0ROWS * RW;          // 2944
constexpr int S1N = S1ROWS * RW;          // 2560
constexpr int SMEM_FLOATS = WAN + WBN + S0N + S1N;  // 25664 -> 102656 B
}

typedef unsigned long long ull;

__device__ __forceinline__ ull pk2(float a, float b) {
    ull r; asm("mov.b64 %0, {%1, %2};" : "=l"(r) : "f"(a), "f"(b)); return r;
}
__device__ __forceinline__ void fma2(ull &d, ull a, ull b) {
    asm("fma.rn.f32x2 %0, %1, %2, %0;" : "+l"(d) : "l"(a), "l"(b));
}
__device__ __forceinline__ void unpk2(ull v, float &a, float &b) {
    asm("mov.b64 {%0, %1}, %2;" : "=f"(a), "=f"(b) : "l"(v));
}
__device__ __forceinline__ float sigm(float x) {
    return __fdividef(1.0f, 1.0f + __expf(-x));
}
__device__ __forceinline__ float tanh_(float x) {
    return __fdividef(2.0f, 1.0f + __expf(-2.0f * x)) - 1.0f;
}
// store 4 values duplicated: {a,a,b,b} {c,c,d,d}
__device__ __forceinline__ void st_dup4(float* base, float a, float b, float c, float d) {
    ulonglong2 v; v.x = pk2(a, a); v.y = pk2(b, b);
    *(ulonglong2*)base = v;
    ulonglong2 u; u.x = pk2(c, c); u.y = pk2(d, d);
    *(ulonglong2*)(base + 4) = u;
}

// 40-k gate accumulation over one duplicated state buffer half (4 batches)
__device__ __forceinline__ void acc40d(const float* __restrict__ hbase,
                                       const float* __restrict__ wbase,
                                       ull aif[4], ull ago[4]) {
    #pragma unroll
    for (int k = 0; k < HP; ++k) {
        ulonglong2 h01 = *(const ulonglong2*)(hbase + k * RW);      // {h0,h0},{h1,h1}
        ulonglong2 h23 = *(const ulonglong2*)(hbase + k * RW + 4);  // {h2,h2},{h3,h3}
        ulonglong2 w   = *(const ulonglong2*)(wbase + k * (4 * HP)); // {wi,wf},{wg,wo}
        fma2(aif[0], h01.x, w.x); fma2(ago[0], h01.x, w.y);
        fma2(aif[1], h01.y, w.x); fma2(ago[1], h01.y, w.y);
        fma2(aif[2], h23.x, w.x); fma2(ago[2], h23.x, w.y);
        fma2(aif[3], h23.y, w.x); fma2(ago[3], h23.y, w.y);
    }
}

__global__ void __launch_bounds__(NTHR, 1) lstm_kernel(
    const float* __restrict__ x,    const float* __restrict__ Wih0,
    const float* __restrict__ Whh0, const float* __restrict__ b0,
    const float* __restrict__ Wih1, const float* __restrict__ Whh1,
    const float* __restrict__ b1,   const float* __restrict__ Wc,
    const float* __restrict__ bc,   float* __restrict__ out)
{
    extern __shared__ float sm[];
    float* WA  = sm;            // [k][q][4]={wi,wf,wg,wo}, k: 0..5 x, 6..45 h0
    float* WB  = WA + WAN;      // [k][q][4],               k: 0..39 h0, 40..79 h1
    float* s0d = WB + WBN;      // duplicated rows: x dbl-buf + h0 dbl-buf
    float* s1d = s0d + S0N;     // duplicated rows: h1 dbl-buf

    const int tid = threadIdx.x;
    const int grp = tid >= GRP;          // 0 = layer0 (A), 1 = layer1 (B)
    const int lt  = tid - grp * GRP;
    const int px  = lt & 3;              // 0..3, 4 batches each
    const int q   = lt >> 2;             // 0..39
    const int bb0 = blockIdx.x * BT + 4 * px;

    // ---- stage weights (zero-padded units / k rows) ----
    for (int idx = tid; idx < WAN; idx += NTHR) {
        int g = idx & 3, qq = (idx >> 2) % HP, k = idx / (4 * HP);
        float v = 0.0f;
        if (qq < H) {
            int row = g * H + qq;
            if (k < NI)          v = Wih0[row * NI + k];
            else { int kk = k - NI; if (kk < H) v = Whh0[row * H + kk]; }
        }
        WA[idx] = v;
    }
    for (int idx = tid; idx < WBN; idx += NTHR) {
        int g = idx & 3, qq = (idx >> 2) % HP, k = idx / (4 * HP);
        float v = 0.0f;
        if (qq < H) {
            int row = g * H + qq;
            if (k < HP) { if (k < H) v = Wih1[row * H + k]; }
            else        { int kk = k - HP; if (kk < H) v = Whh1[row * H + kk]; }
        }
        WB[idx] = v;
    }
    for (int idx = tid; idx < S0N; idx += NTHR) s0d[idx] = 0.0f;
    for (int idx = tid; idx < S1N; idx += NTHR) s1d[idx] = 0.0f;

    // ---- per-thread packed biases for this thread's layer ----
    ull bif, bgo;
    if (q < H) {
        const float* b = grp ? b1 : b0;
        bif = pk2(b[q], b[H + q]);
        bgo = pk2(b[2 * H + q], b[3 * H + q]);
    } else {
        bif = bgo = pk2(0.0f, 0.0f);
    }

    // ---- x(0) into x buffer 0 (duplicated) ----
    if (grp == 0 && q < NI) {
        float x0 = x[(size_t)(bb0 + 0) * Tt * NI + q];
        float x1 = x[(size_t)(bb0 + 1) * Tt * NI + q];
        float x2 = x[(size_t)(bb0 + 2) * Tt * NI + q];
        float x3 = x[(size_t)(bb0 + 3) * Tt * NI + q];
        st_dup4(s0d + q * RW + 8 * px, x0, x1, x2, x3);
    }
    __syncthreads();

    float cst[4] = {0.f, 0.f, 0.f, 0.f};   // A: layer-0 c; B: layer-1 c
    const int hoff = 8 * px;

    // iteration it: A computes layer0 step it (it < Tt);
    //               B computes layer1 step it-1 (it >= 1).
    for (int it = 0; it <= Tt; ++it) {
        const int p  = it & 1;
        const int nb = p ^ 1;

        if (grp == 0) {
            if (it < Tt) {
                // x_{t+1} prefetch (in flight during compute)
                float xn0 = 0.f, xn1 = 0.f, xn2 = 0.f, xn3 = 0.f;
                if (q < NI && it + 1 < Tt) {
                    size_t o = (size_t)(it + 1) * NI + q;
                    xn0 = x[(size_t)(bb0 + 0) * Tt * NI + o];
                    xn1 = x[(size_t)(bb0 + 1) * Tt * NI + o];
                    xn2 = x[(size_t)(bb0 + 2) * Tt * NI + o];
                    xn3 = x[(size_t)(bb0 + 3) * Tt * NI + o];
                }
                ull aif[4], ago[4];
                #pragma unroll
                for (int j = 0; j < 4; ++j) { aif[j] = bif; ago[j] = bgo; }
                const float* wa = WA + 4 * q;
                const float* hx = s0d + p * NI * RW + hoff;     // x buf p (dup)
                #pragma unroll
                for (int k = 0; k < NI; ++k) {
                    ulonglong2 h01 = *(const ulonglong2*)(hx + k * RW);
                    ulonglong2 h23 = *(const ulonglong2*)(hx + k * RW + 4);
                    ulonglong2 w   = *(const ulonglong2*)(wa + k * (4 * HP));
                    fma2(aif[0], h01.x, w.x); fma2(ago[0], h01.x, w.y);
                    fma2(aif[1], h01.y, w.x); fma2(ago[1], h01.y, w.y);
                    fma2(aif[2], h23.x, w.x); fma2(ago[2], h23.x, w.y);
                    fma2(aif[3], h23.y, w.x); fma2(ago[3], h23.y, w.y);
                }
                acc40d(s0d + (2 * NI + p * HP) * RW + hoff,     // h0 buf p (dup)
                       WA + NI * (4 * HP) + 4 * q, aif, ago);
                float hr[4];
                #pragma unroll
                for (int j = 0; j < 4; ++j) {
                    float gi, gf, gg, go;
                    unpk2(aif[j], gi, gf); unpk2(ago[j], gg, go);
                    float i = sigm(gi), f = sigm(gf), g = tanh_(gg), o = sigm(go);
                    cst[j] = f * cst[j] + i * g;
                    hr[j] = o * tanh_(cst[j]);
                }
                // writes -> nb buffers only (duplicated)
                st_dup4(s0d + (2 * NI + nb * HP + q) * RW + hoff,
                        hr[0], hr[1], hr[2], hr[3]);
                if (q < NI && it + 1 < Tt)
                    st_dup4(s0d + (nb * NI + q) * RW + hoff, xn0, xn1, xn2, xn3);
            }
        } else {
            if (it >= 1) {
                ull aif[4], ago[4];
                #pragma unroll
                for (int j = 0; j < 4; ++j) { aif[j] = bif; ago[j] = bgo; }
                // h0(it-1) in s0 h0 buf p (same dup rows A reads)
                acc40d(s0d + (2 * NI + p * HP) * RW + hoff, WB + 4 * q, aif, ago);
                // h1(it-2) in s1 buf p
                acc40d(s1d + p * HP * RW + hoff, WB + HP * (4 * HP) + 4 * q, aif, ago);
                float hr[4];
                #pragma unroll
                for (int j = 0; j < 4; ++j) {
                    float gi, gf, gg, go;
                    unpk2(aif[j], gi, gf); unpk2(ago[j], gg, go);
                    float i = sigm(gi), f = sigm(gf), g = tanh_(gg), o = sigm(go);
                    cst[j] = f * cst[j] + i * g;
                    hr[j] = o * tanh_(cst[j]);
                }
                st_dup4(s1d + (nb * HP + q) * RW + hoff, hr[0], hr[1], hr[2], hr[3]);
            }
        }

        __syncthreads();   // single barrier: nb writes visible, p reads done
    }

    // ---- final projection from h1(Tt-1) in buf (Tt+1)&1 (dup rows) ----
    if (grp == 0 && q < Cc) {
        const int bufL = (Tt + 1) & 1;
        const float* hl = s1d + bufL * HP * RW + hoff;
        float a0 = bc[q], a1 = a0, a2 = a0, a3 = a0;
        #pragma unroll
        for (int k = 0; k < H; ++k) {
            float w = Wc[q * H + k];
            a0 += w * hl[k * RW + 0];
            a1 += w * hl[k * RW + 2];
            a2 += w * hl[k * RW + 4];
            a3 += w * hl[k * RW + 6];
        }
        out[(size_t)(bb0 + 0) * Cc + q] = a0;
        out[(size_t)(bb0 + 1) * Cc + q] = a1;
        out[(size_t)(bb0 + 2) * Cc + q] = a2;
        out[(size_t)(bb0 + 3) * Cc + q] = a3;
    }
}

extern "C" void kernel_launch(void* const* d_in, const int* in_sizes, int n_in,
                              void* d_out, int out_size) {
    const float* x    = (const float*)d_in[0];
    const float* Wih0 = (const float*)d_in[1];
    const float* Whh0 = (const float*)d_in[2];
    const float* b0   = (const float*)d_in[3];
    const float* Wih1 = (const float*)d_in[4];
    const float* Whh1 = (const float*)d_in[5];
    const float* b1   = (const float*)d_in[6];
    const float* Wc   = (const float*)d_in[7];
    const float* bc   = (const float*)d_in[8];

    const int smem_bytes = SMEM_FLOATS * (int)sizeof(float);
    cudaFuncSetAttribute(lstm_kernel, cudaFuncAttributeMaxDynamicSharedMemorySize, smem_bytes);
    lstm_kernel<<<Bsz / BT, NTHR, smem_bytes>>>(
        x, Wih0, Whh0, b0, Wih1, Whh1, b1, Wc, bc, (float*)d_out);
}

// round 16
// speedup vs baseline: 1.0038x; 1.0038x over previous
#include <cuda_runtime.h>

// 2-layer LSTM (B=2048, T=1024, I=6, H=38) + projection (C=8), fp32.
// grid=128 persistent blocks, 16 batches/block, 320 threads, ONE barrier/step.
// R11 structure + three fixes:
//  (1) warp-role permutation (B on warps {2,3,6,7,9}) balances per-SMSP FMA:
//      worst SMSP {A,A,B}=164 warp-k (was {A,B,B}=206).
//  (2) k loops trimmed to H=38 (padded h rows are exactly zero).
//  (3) tanh.approx.f32 activations: 1 MUFU per gate (was 2), shorter tail.
// Thread = (px 0..3, q 0..39), owns 4 batches. Per k:
//   1x LDS.128 W + 1x LDS.128 h + 4 ALU splats + 8 fma.rn.f32x2 = 16 MACs.

namespace {
constexpr int Bsz = 2048, Tt = 1024, NI = 6, H = 38, HP = 40, Cc = 8;
constexpr int BT = 16;             // batches per block
constexpr int GRP = 160;           // active threads per group (5 warps)
constexpr int NTHR = 2 * GRP;      // 320
constexpr unsigned BMASK = 0x2CCu; // warps 2,3,6,7,9 -> group B
constexpr int WAN = (NI + HP) * HP * 4;   // 7360 floats
constexpr int WBN = (HP + HP) * HP * 4;   // 12800 floats
// s0 rows (BT floats): x dbl-buf [0..2*NI), h0 dbl-buf [2*NI..2*NI+2*HP)
// s1 rows: h1 dbl-buf [0..2*HP)
constexpr int S0ROWS = 2 * NI + 2 * HP;   // 92
constexpr int S1ROWS = 2 * HP;            // 80
constexpr int S0N = S0ROWS * BT;          // 1472
constexpr int S1N = S1ROWS * BT;          // 1280
constexpr int SMEM_FLOATS = WAN + WBN + S0N + S1N;  // 22912 -> 91648 B
}

typedef unsigned long long ull;

__device__ __forceinline__ ull pk2(float a, float b) {
    ull r; asm("mov.b64 %0, {%1, %2};" : "=l"(r) : "f"(a), "f"(b)); return r;
}
__device__ __forceinline__ ull splat(float v) {
    ull r; asm("mov.b64 %0, {%1, %1};" : "=l"(r) : "f"(v)); return r;
}
__device__ __forceinline__ void fma2(ull &d, ull a, ull b) {
    asm("fma.rn.f32x2 %0, %1, %2, %0;" : "+l"(d) : "l"(a), "l"(b));
}
__device__ __forceinline__ void unpk2(ull v, float &a, float &b) {
    asm("mov.b64 {%0, %1}, %2;" : "=f"(a), "=f"(b) : "l"(v));
}
__device__ __forceinline__ float tanha(float x) {
    float r; asm("tanh.approx.f32 %0, %1;" : "=f"(r) : "f"(x)); return r;
}
__device__ __forceinline__ float sigm(float x) {
    return fmaf(0.5f, tanha(0.5f * x), 0.5f);
}

// 38-k gate accumulation over one state buffer half (4 batches)
__device__ __forceinline__ void acc38(const float* __restrict__ hbase,
                                      const float* __restrict__ wbase,
                                      ull aif[4], ull ago[4]) {
    #pragma unroll
    for (int k = 0; k < H; ++k) {
        float4 hv = *(const float4*)(hbase + k * BT);
        ulonglong2 w = *(const ulonglong2*)(wbase + k * (4 * HP));
        ull h0s = splat(hv.x), h1s = splat(hv.y), h2s = splat(hv.z), h3s = splat(hv.w);
        fma2(aif[0], h0s, w.x); fma2(ago[0], h0s, w.y);
        fma2(aif[1], h1s, w.x); fma2(ago[1], h1s, w.y);
        fma2(aif[2], h2s, w.x); fma2(ago[2], h2s, w.y);
        fma2(aif[3], h3s, w.x); fma2(ago[3], h3s, w.y);
    }
}

__global__ void __launch_bounds__(NTHR, 1) lstm_kernel(
    const float* __restrict__ x,    const float* __restrict__ Wih0,
    const float* __restrict__ Whh0, const float* __restrict__ b0,
    const float* __restrict__ Wih1, const float* __restrict__ Whh1,
    const float* __restrict__ b1,   const float* __restrict__ Wc,
    const float* __restrict__ bc,   float* __restrict__ out)
{
    extern __shared__ float sm[];
    float* WA = sm;             // [k][q][4]={wi,wf,wg,wo}, k: 0..5 x, 6..45 h0
    float* WB = WA + WAN;       // [k][q][4],               k: 0..39 h0, 40..79 h1
    float* s0 = WB + WBN;       // x dbl-buf rows + h0 dbl-buf rows
    float* s1 = s0 + S0N;       // h1 dbl-buf rows

    const int tid  = threadIdx.x;
    const int wid  = tid >> 5;
    const int lane = tid & 31;
    const int grp  = (BMASK >> wid) & 1;              // 0 = layer0 (A), 1 = layer1 (B)
    const unsigned mymask = grp ? BMASK : ~BMASK;
    const int rank = __popc(mymask & ((1u << wid) - 1u));
    const int lt   = rank * 32 + lane;                // 0..159 within group
    const int px   = lt & 3;                          // 0..3, 4 batches each
    const int q    = lt >> 2;                         // 0..39
    const int bb0  = blockIdx.x * BT + 4 * px;

    // ---- stage weights (zero-padded units / k rows) ----
    for (int idx = tid; idx < WAN; idx += NTHR) {
        int g = idx & 3, qq = (idx >> 2) % HP, k = idx / (4 * HP);
        float v = 0.0f;
        if (qq < H) {
            int row = g * H + qq;
            if (k < NI)          v = Wih0[row * NI + k];
            else { int kk = k - NI; if (kk < H) v = Whh0[row * H + kk]; }
        }
        WA[idx] = v;
    }
    for (int idx = tid; idx < WBN; idx += NTHR) {
        int g = idx & 3, qq = (idx >> 2) % HP, k = idx / (4 * HP);
        float v = 0.0f;
        if (qq < H) {
            int row = g * H + qq;
            if (k < HP) { if (k < H) v = Wih1[row * H + k]; }
            else        { int kk = k - HP; if (kk < H) v = Whh1[row * H + kk]; }
        }
        WB[idx] = v;
    }
    for (int idx = tid; idx < S0N; idx += NTHR) s0[idx] = 0.0f;
    for (int idx = tid; idx < S1N; idx += NTHR) s1[idx] = 0.0f;

    // ---- per-thread packed biases for this thread's layer ----
    ull bif, bgo;
    if (q < H) {
        const float* b = grp ? b1 : b0;
        bif = pk2(b[q], b[H + q]);
        bgo = pk2(b[2 * H + q], b[3 * H + q]);
    } else {
        bif = bgo = pk2(0.0f, 0.0f);
    }

    // ---- x(0) into x buffer 0 ----
    if (grp == 0 && q < NI) {
        float4 xv;
        xv.x = x[(size_t)(bb0 + 0) * Tt * NI + q];
        xv.y = x[(size_t)(bb0 + 1) * Tt * NI + q];
        xv.z = x[(size_t)(bb0 + 2) * Tt * NI + q];
        xv.w = x[(size_t)(bb0 + 3) * Tt * NI + q];
        *(float4*)(s0 + q * BT + 4 * px) = xv;
    }
    __syncthreads();

    float cst[4] = {0.f, 0.f, 0.f, 0.f};   // A: layer-0 c; B: layer-1 c
    const int hoff = 4 * px;

    // iteration it: A computes layer0 step it (it < Tt);
    //               B computes layer1 step it-1 (it >= 1).
    for (int it = 0; it <= Tt; ++it) {
        const int p  = it & 1;
        const int nb = p ^ 1;

        if (grp == 0) {
            if (it < Tt) {
                // x_{t+1} prefetch (in flight during compute)
                float xn0 = 0.f, xn1 = 0.f, xn2 = 0.f, xn3 = 0.f;
                if (q < NI && it + 1 < Tt) {
                    size_t o = (size_t)(it + 1) * NI + q;
                    xn0 = x[(size_t)(bb0 + 0) * Tt * NI + o];
                    xn1 = x[(size_t)(bb0 + 1) * Tt * NI + o];
                    xn2 = x[(size_t)(bb0 + 2) * Tt * NI + o];
                    xn3 = x[(size_t)(bb0 + 3) * Tt * NI + o];
                }
                ull aif[4], ago[4];
                #pragma unroll
                for (int j = 0; j < 4; ++j) { aif[j] = bif; ago[j] = bgo; }
                const float* wa = WA + 4 * q;
                const float* hx = s0 + p * NI * BT + hoff;      // x buf p
                #pragma unroll
                for (int k = 0; k < NI; ++k) {
                    float4 hv = *(const float4*)(hx + k * BT);
                    ulonglong2 w = *(const ulonglong2*)(wa + k * (4 * HP));
                    ull h0s = splat(hv.x), h1s = splat(hv.y), h2s = splat(hv.z), h3s = splat(hv.w);
                    fma2(aif[0], h0s, w.x); fma2(ago[0], h0s, w.y);
                    fma2(aif[1], h1s, w.x); fma2(ago[1], h1s, w.y);
                    fma2(aif[2], h2s, w.x); fma2(ago[2], h2s, w.y);
                    fma2(aif[3], h3s, w.x); fma2(ago[3], h3s, w.y);
                }
                acc38(s0 + (2 * NI + p * HP) * BT + hoff,       // h0 buf p
                      WA + NI * (4 * HP) + 4 * q, aif, ago);
                float hr[4];
                #pragma unroll
                for (int j = 0; j < 4; ++j) {
                    float gi, gf, gg, go;
                    unpk2(aif[j], gi, gf); unpk2(ago[j], gg, go);
                    float i = sigm(gi), f = sigm(gf), g = tanha(gg), o = sigm(go);
                    cst[j] = f * cst[j] + i * g;
                    hr[j] = o * tanha(cst[j]);
                }
                // writes -> nb buffers only
                *(float4*)(s0 + (2 * NI + nb * HP + q) * BT + hoff) =
                    make_float4(hr[0], hr[1], hr[2], hr[3]);
                if (q < NI && it + 1 < Tt)
                    *(float4*)(s0 + (nb * NI + q) * BT + hoff) =
                        make_float4(xn0, xn1, xn2, xn3);
            }
        } else {
            if (it >= 1) {
                ull aif[4], ago[4];
                #pragma unroll
                for (int j = 0; j < 4; ++j) { aif[j] = bif; ago[j] = bgo; }
                // h0(it-1) in s0 h0 buf p (same rows A reads)
                acc38(s0 + (2 * NI + p * HP) * BT + hoff, WB + 4 * q, aif, ago);
                // h1(it-2) in s1 buf p
                acc38(s1 + p * HP * BT + hoff, WB + HP * (4 * HP) + 4 * q, aif, ago);
                float hr[4];
                #pragma unroll
                for (int j = 0; j < 4; ++j) {
                    float gi, gf, gg, go;
                    unpk2(aif[j], gi, gf); unpk2(ago[j], gg, go);
                    float i = sigm(gi), f = sigm(gf), g = tanha(gg), o = sigm(go);
                    cst[j] = f * cst[j] + i * g;
                    hr[j] = o * tanha(cst[j]);
                }
                *(float4*)(s1 + (nb * HP + q) * BT + hoff) =
                    make_float4(hr[0], hr[1], hr[2], hr[3]);
            }
        }

        __syncthreads();   // single barrier: nb writes visible, p reads done
    }

    // ---- final projection from h1(Tt-1) in buf (Tt+1)&1 ----
    if (grp == 0 && q < Cc) {
        const int bufL = (Tt + 1) & 1;
        const float* hl = s1 + bufL * HP * BT + hoff;
        float a0 = bc[q], a1 = a0, a2 = a0, a3 = a0;
        #pragma unroll
        for (int k = 0; k < H; ++k) {
            float w = Wc[q * H + k];
            float4 hv = *(const float4*)(hl + k * BT);
            a0 += w * hv.x; a1 += w * hv.y; a2 += w * hv.z; a3 += w * hv.w;
        }
        out[(size_t)(bb0 + 0) * Cc + q] = a0;
        out[(size_t)(bb0 + 1) * Cc + q] = a1;
        out[(size_t)(bb0 + 2) * Cc + q] = a2;
        out[(size_t)(bb0 + 3) * Cc + q] = a3;
    }
}

extern "C" void kernel_launch(void* const* d_in, const int* in_sizes, int n_in,
                              void* d_out, int out_size) {
    const float* x    = (const float*)d_in[0];
    const float* Wih0 = (const float*)d_in[1];
    const float* Whh0 = (const float*)d_in[2];
    const float* b0   = (const float*)d_in[3];
    const float* Wih1 = (const float*)d_in[4];
    const float* Whh1 = (const float*)d_in[5];
    const float* b1   = (const float*)d_in[6];
    const float* Wc   = (const float*)d_in[7];
    const float* bc   = (const float*)d_in[8];

    const int smem_bytes = SMEM_FLOATS * (int)sizeof(float);
    cudaFuncSetAttribute(lstm_kernel, cudaFuncAttributeMaxDynamicSharedMemorySize, smem_bytes);
    lstm_kernel<<<Bsz / BT, NTHR, smem_bytes>>>(
        x, Wih0, Whh0, b0, Wih1, Whh1, b1, Wc, bc, (float*)d_out);
}

// round 17
// speedup vs baseline: 1.4411x; 1.4356x over previous
#include <cuda_runtime.h>

// 2-layer LSTM (B=2048, T=1024, I=6, H=38) + projection (C=8), fp32.
// EXACT R11 structure (best: 2735us). Single change: activations use
// tanh.approx.f32 (1 MUFU) and sigm(x)=0.5*tanh(0.5x)+0.5 -> MUFU work
// per thread-step halves (40 -> 20) and the serial activation tail shortens.
// grid=128 persistent blocks, 16 batches/block, 320 threads, ONE barrier/step.
//   group A (0..159):   layer 0 @ step t
//   group B (160..319): layer 1 @ step t-1
// x/h0/h1 double-buffered by parity: reads p, writes nb.
// Thread = (px 0..3, q 0..39), owns 4 batches. Per k:
//   1x LDS.128 W + 1x LDS.128 h + 4 ALU splats + 8 fma.rn.f32x2 = 16 MACs.

namespace {
constexpr int Bsz = 2048, Tt = 1024, NI = 6, H = 38, HP = 40, Cc = 8;
constexpr int BT = 16;             // batches per block
constexpr int GRP = 160;           // threads per group
constexpr int NTHR = 2 * GRP;      // 320
constexpr int WAN = (NI + HP) * HP * 4;   // 7360 floats
constexpr int WBN = (HP + HP) * HP * 4;   // 12800 floats
// s0 rows (BT floats): x dbl-buf [0..2*NI), h0 dbl-buf [2*NI..2*NI+2*HP)
// s1 rows: h1 dbl-buf [0..2*HP)
constexpr int S0ROWS = 2 * NI + 2 * HP;   // 92
constexpr int S1ROWS = 2 * HP;            // 80
constexpr int S0N = S0ROWS * BT;          // 1472
constexpr int S1N = S1ROWS * BT;          // 1280
constexpr int SMEM_FLOATS = WAN + WBN + S0N + S1N;  // 22912 -> 91648 B
}

typedef unsigned long long ull;

__device__ __forceinline__ ull pk2(float a, float b) {
    ull r; asm("mov.b64 %0, {%1, %2};" : "=l"(r) : "f"(a), "f"(b)); return r;
}
__device__ __forceinline__ ull splat(float v) {
    ull r; asm("mov.b64 %0, {%1, %1};" : "=l"(r) : "f"(v)); return r;
}
__device__ __forceinline__ void fma2(ull &d, ull a, ull b) {
    asm("fma.rn.f32x2 %0, %1, %2, %0;" : "+l"(d) : "l"(a), "l"(b));
}
__device__ __forceinline__ void unpk2(ull v, float &a, float &b) {
    asm("mov.b64 {%0, %1}, %2;" : "=f"(a), "=f"(b) : "l"(v));
}
__device__ __forceinline__ float tanha(float x) {
    float r; asm("tanh.approx.f32 %0, %1;" : "=f"(r) : "f"(x)); return r;
}
__device__ __forceinline__ float sigm(float x) {
    return fmaf(0.5f, tanha(0.5f * x), 0.5f);
}

// 40-k gate accumulation over one state buffer half (4 batches)
__device__ __forceinline__ void acc40(const float* __restrict__ hbase,
                                      const float* __restrict__ wbase,
                                      ull aif[4], ull ago[4]) {
    #pragma unroll
    for (int k = 0; k < HP; ++k) {
        float4 hv = *(const float4*)(hbase + k * BT);
        ulonglong2 w = *(const ulonglong2*)(wbase + k * (4 * HP));
        ull h0s = splat(hv.x), h1s = splat(hv.y), h2s = splat(hv.z), h3s = splat(hv.w);
        fma2(aif[0], h0s, w.x); fma2(ago[0], h0s, w.y);
        fma2(aif[1], h1s, w.x); fma2(ago[1], h1s, w.y);
        fma2(aif[2], h2s, w.x); fma2(ago[2], h2s, w.y);
        fma2(aif[3], h3s, w.x); fma2(ago[3], h3s, w.y);
    }
}

__global__ void __launch_bounds__(NTHR, 1) lstm_kernel(
    const float* __restrict__ x,    const float* __restrict__ Wih0,
    const float* __restrict__ Whh0, const float* __restrict__ b0,
    const float* __restrict__ Wih1, const float* __restrict__ Whh1,
    const float* __restrict__ b1,   const float* __restrict__ Wc,
    const float* __restrict__ bc,   float* __restrict__ out)
{
    extern __shared__ float sm[];
    float* WA = sm;             // [k][q][4]={wi,wf,wg,wo}, k: 0..5 x, 6..45 h0
    float* WB = WA + WAN;       // [k][q][4],               k: 0..39 h0, 40..79 h1
    float* s0 = WB + WBN;       // x dbl-buf rows + h0 dbl-buf rows
    float* s1 = s0 + S0N;       // h1 dbl-buf rows

    const int tid = threadIdx.x;
    const int grp = tid >= GRP;          // 0 = layer0 (A), 1 = layer1 (B)
    const int lt  = tid - grp * GRP;
    const int px  = lt & 3;              // 0..3, 4 batches each
    const int q   = lt >> 2;             // 0..39
    const int bb0 = blockIdx.x * BT + 4 * px;

    // ---- stage weights (zero-padded units / k rows) ----
    for (int idx = tid; idx < WAN; idx += NTHR) {
        int g = idx & 3, qq = (idx >> 2) % HP, k = idx / (4 * HP);
        float v = 0.0f;
        if (qq < H) {
            int row = g * H + qq;
            if (k < NI)          v = Wih0[row * NI + k];
            else { int kk = k - NI; if (kk < H) v = Whh0[row * H + kk]; }
        }
        WA[idx] = v;
    }
    for (int idx = tid; idx < WBN; idx += NTHR) {
        int g = idx & 3, qq = (idx >> 2) % HP, k = idx / (4 * HP);
        float v = 0.0f;
        if (qq < H) {
            int row = g * H + qq;
            if (k < HP) { if (k < H) v = Wih1[row * H + k]; }
            else        { int kk = k - HP; if (kk < H) v = Whh1[row * H + kk]; }
        }
        WB[idx] = v;
    }
    for (int idx = tid; idx < S0N; idx += NTHR) s0[idx] = 0.0f;
    for (int idx = tid; idx < S1N; idx += NTHR) s1[idx] = 0.0f;

    // ---- per-thread packed biases for this thread's layer ----
    ull bif, bgo;
    if (q < H) {
        const float* b = grp ? b1 : b0;
        bif = pk2(b[q], b[H + q]);
        bgo = pk2(b[2 * H + q], b[3 * H + q]);
    } else {
        bif = bgo = pk2(0.0f, 0.0f);
    }

    // ---- x(0) into x buffer 0 ----
    if (grp == 0 && q < NI) {
        float4 xv;
        xv.x = x[(size_t)(bb0 + 0) * Tt * NI + q];
        xv.y = x[(size_t)(bb0 + 1) * Tt * NI + q];
        xv.z = x[(size_t)(bb0 + 2) * Tt * NI + q];
        xv.w = x[(size_t)(bb0 + 3) * Tt * NI + q];
        *(float4*)(s0 + q * BT + 4 * px) = xv;
    }
    __syncthreads();

    float cst[4] = {0.f, 0.f, 0.f, 0.f};   // A: layer-0 c; B: layer-1 c
    const int hoff = 4 * px;

    // iteration it: A computes layer0 step it (it < Tt);
    //               B computes layer1 step it-1 (it >= 1).
    for (int it = 0; it <= Tt; ++it) {
        const int p  = it & 1;
        const int nb = p ^ 1;

        if (grp == 0) {
            if (it < Tt) {
                // x_{t+1} prefetch (in flight during compute)
                float xn0 = 0.f, xn1 = 0.f, xn2 = 0.f, xn3 = 0.f;
                if (q < NI && it + 1 < Tt) {
                    size_t o = (size_t)(it + 1) * NI + q;
                    xn0 = x[(size_t)(bb0 + 0) * Tt * NI + o];
                    xn1 = x[(size_t)(bb0 + 1) * Tt * NI + o];
                    xn2 = x[(size_t)(bb0 + 2) * Tt * NI + o];
                    xn3 = x[(size_t)(bb0 + 3) * Tt * NI + o];
                }
                ull aif[4], ago[4];
                #pragma unroll
                for (int j = 0; j < 4; ++j) { aif[j] = bif; ago[j] = bgo; }
                const float* wa = WA + 4 * q;
                const float* hx = s0 + p * NI * BT + hoff;      // x buf p
                #pragma unroll
                for (int k = 0; k < NI; ++k) {
                    float4 hv = *(const float4*)(hx + k * BT);
                    ulonglong2 w = *(const ulonglong2*)(wa + k * (4 * HP));
                    ull h0s = splat(hv.x), h1s = splat(hv.y), h2s = splat(hv.z), h3s = splat(hv.w);
                    fma2(aif[0], h0s, w.x); fma2(ago[0], h0s, w.y);
                    fma2(aif[1], h1s, w.x); fma2(ago[1], h1s, w.y);
                    fma2(aif[2], h2s, w.x); fma2(ago[2], h2s, w.y);
                    fma2(aif[3], h3s, w.x); fma2(ago[3], h3s, w.y);
                }
                acc40(s0 + (2 * NI + p * HP) * BT + hoff,       // h0 buf p
                      WA + NI * (4 * HP) + 4 * q, aif, ago);
                float hr[4];
                #pragma unroll
                for (int j = 0; j < 4; ++j) {
                    float gi, gf, gg, go;
                    unpk2(aif[j], gi, gf); unpk2(ago[j], gg, go);
                    float i = sigm(gi), f = sigm(gf), g = tanha(gg), o = sigm(go);
                    cst[j] = f * cst[j] + i * g;
                    hr[j] = o * tanha(cst[j]);
                }
                // writes -> nb buffers only
                *(float4*)(s0 + (2 * NI + nb * HP + q) * BT + hoff) =
                    make_float4(hr[0], hr[1], hr[2], hr[3]);
                if (q < NI && it + 1 < Tt)
                    *(float4*)(s0 + (nb * NI + q) * BT + hoff) =
                        make_float4(xn0, xn1, xn2, xn3);
            }
        } else {
            if (it >= 1) {
                ull aif[4], ago[4];
                #pragma unroll
                for (int j = 0; j < 4; ++j) { aif[j] = bif; ago[j] = bgo; }
                // h0(it-1) in s0 h0 buf p (same rows A reads)
                acc40(s0 + (2 * NI + p * HP) * BT + hoff, WB + 4 * q, aif, ago);
                // h1(it-2) in s1 buf p
                acc40(s1 + p * HP * BT + hoff, WB + HP * (4 * HP) + 4 * q, aif, ago);
                float hr[4];
                #pragma unroll
                for (int j = 0; j < 4; ++j) {
                    float gi, gf, gg, go;
                    unpk2(aif[j], gi, gf); unpk2(ago[j], gg, go);
                    float i = sigm(gi), f = sigm(gf), g = tanha(gg), o = sigm(go);
                    cst[j] = f * cst[j] + i * g;
                    hr[j] = o * tanha(cst[j]);
                }
                *(float4*)(s1 + (nb * HP + q) * BT + hoff) =
                    make_float4(hr[0], hr[1], hr[2], hr[3]);
            }
        }

        __syncthreads();   // single barrier: nb writes visible, p reads done
    }

    // ---- final projection from h1(Tt-1) in buf (Tt+1)&1 ----
    if (grp == 0 && q < Cc) {
        const int bufL = (Tt + 1) & 1;
        const float* hl = s1 + bufL * HP * BT + hoff;
        float a0 = bc[q], a1 = a0, a2 = a0, a3 = a0;
        #pragma unroll
        for (int k = 0; k < H; ++k) {
            float w = Wc[q * H + k];
            float4 hv = *(const float4*)(hl + k * BT);
            a0 += w * hv.x; a1 += w * hv.y; a2 += w * hv.z; a3 += w * hv.w;
        }
        out[(size_t)(bb0 + 0) * Cc + q] = a0;
        out[(size_t)(bb0 + 1) * Cc + q] = a1;
        out[(size_t)(bb0 + 2) * Cc + q] = a2;
        out[(size_t)(bb0 + 3) * Cc + q] = a3;
    }
}

extern "C" void kernel_launch(void* const* d_in, const int* in_sizes, int n_in,
                              void* d_out, int out_size) {
    const float* x    = (const float*)d_in[0];
    const float* Wih0 = (const float*)d_in[1];
    const float* Whh0 = (const float*)d_in[2];
    const float* b0   = (const float*)d_in[3];
    const float* Wih1 = (const float*)d_in[4];
    const float* Whh1 = (const float*)d_in[5];
    const float* b1   = (const float*)d_in[6];
    const float* Wc   = (const float*)d_in[7];
    const float* bc   = (const float*)d_in[8];

    const int smem_bytes = SMEM_FLOATS * (int)sizeof(float);
    cudaFuncSetAttribute(lstm_kernel, cudaFuncAttributeMaxDynamicSharedMemorySize, smem_bytes);
    lstm_kernel<<<Bsz / BT, NTHR, smem_bytes>>>(
        x, Wih0, Whh0, b0, Wih1, Whh1, b1, Wc, bc, (float*)d_out);
}